// round 5
// baseline (speedup 1.0000x reference)
#include <cuda_runtime.h>

#define THREADS 128
#define Jt 32
#define NT 32          // 1024 / Jt

typedef unsigned long long u64;
typedef unsigned int u32;

__device__ __forceinline__ float tanh_apx(float x) {
    float r; asm("tanh.approx.f32 %0, %1;" : "=f"(r) : "f"(x)); return r;
}
__device__ __forceinline__ float rcp_apx(float x) {
    float r; asm("rcp.approx.f32 %0, %1;" : "=f"(r) : "f"(x)); return r;
}
#define FMA2(d,a,b,c)  asm("fma.rn.f32x2 %0, %1, %2, %3;" : "=l"(d) : "l"(a), "l"(b), "l"(c))
#define ADD2(d,a,b)    asm("add.rn.f32x2 %0, %1, %2;" : "=l"(d) : "l"(a), "l"(b))
#define PACK2(d,x,y)   asm("mov.b64 %0, {%1,%2};" : "=l"(d) : "f"(x), "f"(y))
#define UNPACK2(x,y,d) asm("mov.b64 {%0,%1}, %2;" : "=f"(x), "=f"(y) : "l"(d))

#define NTANH 3                       // pairs 0..2 -> tanh path; 3..7 -> poly path
#define LOG2E 1.4426950408889634f
#define LN2   0.6931471805599453f
#define MAGICF 12582912.0f            // 1.5 * 2^23
#define SGN2  0x8000000080000000ull

__global__ __launch_bounds__(THREADS, 3)
void attn_mlp_kernel(const float* __restrict__ Q, const float* __restrict__ K,
                     const float* __restrict__ bias, const float* __restrict__ mask,
                     float* __restrict__ out, float* __restrict__ attn)
{
    __shared__ float4 ksm[2][Jt * 17];   // double-buffered K tile, pad 17 -> conflict-free
    __shared__ float  red[512];
    __shared__ float  cbuf[2][4];

    const int tid = threadIdx.x;
    const int w   = tid >> 5, l = tid & 31;
    const int jl  = w * 8 + (l & 7);     // j within tile (0..31)
    const int cg  = l >> 3;              // channel group (16 ch each)

    const int row0 = blockIdx.x * 2;     // two i-rows per block, same b
    const int b    = row0 >> 10;

    // Per-pair prescale: tanh pairs use 0.5 (sigmoid = 0.5+0.5*tanh(x/2));
    // poly pairs use log2e (sigmoid = 1/(1+2^-s), s = log2e*(qk+b)).
    u64 q20[8], q21[8], b2[8], s20[8], s21[8];
    {
        const float* q0p = Q + (size_t)row0 * 64 + cg * 16;
        const float* q1p = q0p + 64;
        const float* bp  = bias + cg * 16;
#pragma unroll
        for (int p = 0; p < 8; ++p) {
            float sc = (p < NTANH) ? 0.5f : LOG2E;
            PACK2(q20[p], sc * q0p[2*p], sc * q0p[2*p+1]);
            PACK2(q21[p], sc * q1p[2*p], sc * q1p[2*p+1]);
            PACK2(b2[p],  sc * bp[2*p],  sc * bp[2*p+1]);
            s20[p] = 0ull; s21[p] = 0ull;
        }
    }
    float cnt0 = 0.f, cnt1 = 0.f;

    // packed constants
    u64 MG2, NMG2, NEG1, C0p, C1p, C2p, C3p;
    PACK2(MG2,  MAGICF,  MAGICF);
    PACK2(NMG2, -MAGICF, -MAGICF);
    PACK2(NEG1, -1.0f, -1.0f);
    PACK2(C0p, 0.99999989f, 0.99999989f);
    PACK2(C1p, 0.69315475f, 0.69315475f);
    PACK2(C2p, 0.24015070f, 0.24015070f);
    PACK2(C3p, 0.05585897f, 0.05585897f);

    const float4* Kg  = (const float4*)K + (size_t)b * 1024 * 16;
    const float*  m0p = mask + (size_t)row0 * 1024;
    const float*  m1p = m0p + 1024;
    float*        a0p = attn + (size_t)row0 * 1024;
    float*        a1p = a0p + 1024;

    // prefetch tile 0 into registers
    float4 kpre[4];
#pragma unroll
    for (int u = 0; u < 4; ++u) {
        int f = u * 128 + tid;
        kpre[u] = Kg[(size_t)(f >> 4) * 16 + (f & 15)];
    }

    int buf = 0;
    for (int tile = 0; tile < NT; ++tile) {
#pragma unroll
        for (int u = 0; u < 4; ++u) {
            int f = u * 128 + tid;
            ksm[buf][(f >> 4) * 17 + (f & 15)] = kpre[u];
        }
        __syncthreads();

        if (tile + 1 < NT) {
#pragma unroll
            for (int u = 0; u < 4; ++u) {
                int f = u * 128 + tid;
                kpre[u] = Kg[(size_t)((tile + 1) * Jt + (f >> 4)) * 16 + (f & 15)];
            }
        }

        u64 k2[8];
#pragma unroll
        for (int p4 = 0; p4 < 4; ++p4) {
            float4 kv = ksm[buf][jl * 17 + cg * 4 + p4];
            PACK2(k2[2*p4],   kv.x, kv.y);
            PACK2(k2[2*p4+1], kv.z, kv.w);
        }
        const int   j  = tile * Jt + jl;
        const float m0 = m0p[j], m1 = m1p[j];
        u64 m20, m21; PACK2(m20, m0, m0); PACK2(m21, m1, m1);
        u64 dA0 = 0ull, dA1 = 0ull;   // tanh-path dot partials (scale 0.5)
        u64 dB0 = 0ull, dB1 = 0ull;   // poly-path dot partials (scale log2e)

#pragma unroll
        for (int p = 0; p < 8; ++p) {
            if (p < NTANH) {
                // ---- tanh path (MUFU) ----
                u64 l2, t2; float la, lb;
                FMA2(l2, q20[p], k2[p], b2[p]);
                FMA2(dA0, q20[p], k2[p], dA0);
                UNPACK2(la, lb, l2);
                PACK2(t2, tanh_apx(la), tanh_apx(lb));
                FMA2(s20[p], m20, t2, s20[p]);

                FMA2(l2, q21[p], k2[p], b2[p]);
                FMA2(dA1, q21[p], k2[p], dA1);
                UNPACK2(la, lb, l2);
                PACK2(t2, tanh_apx(la), tanh_apx(lb));
                FMA2(s21[p], m21, t2, s21[p]);
            } else {
                // ---- poly-exp2 path: sigma = 1/(1 + 2^-s), 2^-s on the FMA pipe
#pragma unroll
                for (int r = 0; r < 2; ++r) {
                    u64 qq = r ? q21[p] : q20[p];
                    u64 s2, t2, i2, f2, y2;
                    FMA2(s2, qq, k2[p], b2[p]);          // s = log2e*(qk+b)
                    if (r) { FMA2(dB1, qq, k2[p], dB1); }
                    else   { FMA2(dB0, qq, k2[p], dB0); }
                    u64 ns2 = s2 ^ SGN2;                 // -s  (ALU pipe, sign flip)
                    ADD2(t2, ns2, MG2);                  // t = -s + M  (i = round(-s))
                    ADD2(i2, t2, NMG2);                  // i = t - M   (EXACT, small float)
                    FMA2(f2, i2, NEG1, ns2);             // f = -s - i, f in [-0.5, 0.5]
                    FMA2(y2, C3p, f2, C2p);              // Horner 2^f
                    FMA2(y2, y2, f2, C1p);
                    FMA2(y2, y2, f2, C0p);
                    float tl, th, yl, yh;
                    UNPACK2(tl, th, t2);
                    UNPACK2(yl, yh, y2);
                    u32 pl = __float_as_uint(tl) * 8388608u + __float_as_uint(yl);  // y * 2^i
                    u32 ph = __float_as_uint(th) * 8388608u + __float_as_uint(yh);
                    float dl = __uint_as_float(pl) + 1.0f;
                    float dh = __uint_as_float(ph) + 1.0f;
                    u64 g2; PACK2(g2, rcp_apx(dl), rcp_apx(dh));   // sigma = 1/(1+2^-s)
                    if (r) { FMA2(s21[p], m21, g2, s21[p]); }
                    else   { FMA2(s20[p], m20, g2, s20[p]); }
                }
            }
        }
        if (cg == 0) { cnt0 += m0; cnt1 += m1; }

        // attention logits: Q.K = 2*dotA + ln2*dotB  (exact fp32 path)
        float ax, ay, bx, by;
        UNPACK2(ax, ay, dA0); UNPACK2(bx, by, dB0);
        float d0 = 2.0f * (ax + ay) + LN2 * (bx + by);
        UNPACK2(ax, ay, dA1); UNPACK2(bx, by, dB1);
        float d1 = 2.0f * (ax + ay) + LN2 * (bx + by);
        d0 += __shfl_xor_sync(~0u, d0, 8);
        d0 += __shfl_xor_sync(~0u, d0, 16);
        d1 += __shfl_xor_sync(~0u, d1, 8);
        d1 += __shfl_xor_sync(~0u, d1, 16);
        if (cg == 0) {
            a0p[j] = d0 * m0;
            a1p[j] = d1 * m1;
        }
        buf ^= 1;
    }

    // ---- final reductions ----
#pragma unroll
    for (int p = 0; p < 8; ++p) {
        float x0, y0, x1, y1;
        UNPACK2(x0, y0, s20[p]); UNPACK2(x1, y1, s21[p]);
#pragma unroll
        for (int o = 1; o <= 4; o <<= 1) {
            x0 += __shfl_xor_sync(~0u, x0, o);
            y0 += __shfl_xor_sync(~0u, y0, o);
            x1 += __shfl_xor_sync(~0u, x1, o);
            y1 += __shfl_xor_sync(~0u, y1, o);
        }
        if ((l & 7) == 0) {
            float* rp = red + w * 128 + cg * 32;
            rp[2*p]          = x0;
            rp[2*p + 1]      = y0;
            rp[16 + 2*p]     = x1;
            rp[16 + 2*p + 1] = y1;
        }
    }
    for (int o = 1; o <= 4; o <<= 1) {
        cnt0 += __shfl_xor_sync(~0u, cnt0, o);
        cnt1 += __shfl_xor_sync(~0u, cnt1, o);
    }
    if (l == 0) { cbuf[0][w] = cnt0; cbuf[1][w] = cnt1; }
    __syncthreads();

    {
        const int r  = tid >> 6;
        const int ch = tid & 63;
        float ct = cbuf[r][0] + cbuf[r][1] + cbuf[r][2] + cbuf[r][3];
        float s  = 0.f;
#pragma unroll
        for (int ww = 0; ww < 4; ++ww)
            s += red[ww * 128 + (ch >> 4) * 32 + r * 16 + (ch & 15)];
        // tanh pairs accumulated m*tanh -> 0.5 + 0.5*s/ct ; poly pairs m*sigma -> s/ct
        float v = (((ch & 15) >> 1) < NTANH) ? (0.5f + 0.5f * s / ct) : (s / ct);
        out[(size_t)(row0 + r) * 64 + ch] = v;
    }
}

extern "C" void kernel_launch(void* const* d_in, const int* in_sizes, int n_in,
                              void* d_out, int out_size)
{
    const float* Q    = (const float*)d_in[0];
    const float* K    = (const float*)d_in[1];
    const float* bias = (const float*)d_in[2];
    const float* mask = (const float*)d_in[3];
    float* out  = (float*)d_out;                       // [B, I, C]
    float* attn = out + (size_t)2 * 1024 * 64;         // [B, I, J]
    attn_mlp_kernel<<<1024, THREADS>>>(Q, K, bias, mask, out, attn);
}